// round 4
// baseline (speedup 1.0000x reference)
#include <cuda_runtime.h>
#include <cstdint>
#include <cstddef>

// ---------------- problem constants ----------------
constexpr int TT   = 2048;
constexpr int HH   = 2048;
constexpr int EE   = 64;
constexpr int KTOP = 8;
constexpr int II   = 768;
constexpr int NHH  = 16;
constexpr int DHH  = 128;
constexpr int SII  = 4096;
constexpr int CAPP = 512;

// ---------------- scratch (device globals: allocation-free) ----------------
__device__ float g_hn1   [(size_t)TT*HH];
__device__ float g_qkv   [(size_t)TT*3*HH];
__device__ float g_scores[(size_t)NHH*TT*TT];
__device__ float g_attn  [(size_t)TT*HH];
__device__ float g_x2    [(size_t)TT*HH];
__device__ float g_hn2   [(size_t)TT*HH];
__device__ float g_logits[(size_t)TT*EE];
__device__ int   g_ids   [TT*KTOP];
__device__ float g_wts   [TT*KTOP];
__device__ int   g_pos   [TT*KTOP];
__device__ int   g_cnt   [EE];
__device__ float g_buf   [(size_t)EE*CAPP*HH];
__device__ float g_gu    [(size_t)EE*CAPP*2*II];
__device__ float g_eact  [(size_t)EE*CAPP*II];
__device__ float g_y     [(size_t)EE*CAPP*HH];
__device__ float g_sgu   [(size_t)TT*2*SII];
__device__ float g_sact  [(size_t)TT*SII];
__device__ float g_sres  [(size_t)TT*HH];

// ---------------- generic batched SGEMM ----------------
// C[b] = alpha * A[b] * op(B[b]) (+ R[b]),  op = B (KxN, !TB) or B^T (NxK rows, TB)
// Requires: K % 8 == 0, all leading dims % 4 == 0, 16B-aligned bases (true for all uses).
constexpr int BM = 128, BN = 128, BKT = 8;

template <bool TB>
__global__ __launch_bounds__(256)
void sgemm_k(const float* __restrict__ A, int lda, long long sA,
             const float* __restrict__ B, int ldb, long long sB,
             float*       __restrict__ C, int ldc, long long sC,
             const float* __restrict__ R, int ldr, long long sR,
             int M, int N, int Kd, float alpha,
             const int* __restrict__ rowLimit)
{
    const int bz = blockIdx.z;
    if (rowLimit != nullptr && (int)(blockIdx.y * BM) >= rowLimit[bz]) return;
    A += (long long)bz * sA;
    B += (long long)bz * sB;
    C += (long long)bz * sC;
    if (R) R += (long long)bz * sR;

    __shared__ float As[BKT][BM + 4];
    __shared__ float Bs[BKT][BN + 4];

    const int tid  = threadIdx.x;
    const int tx   = tid & 15;
    const int ty   = tid >> 4;
    const int row0 = blockIdx.y * BM;
    const int col0 = blockIdx.x * BN;

    float acc[8][8];
#pragma unroll
    for (int i = 0; i < 8; i++)
#pragma unroll
        for (int j = 0; j < 8; j++) acc[i][j] = 0.f;

    const int arow  = tid >> 1;          // 0..127
    const int acol  = (tid & 1) * 4;     // 0 or 4
    const int bkrow = tid >> 5;          // 0..7   (!TB)
    const int bncol = (tid & 31) * 4;    // 0..124 (!TB)

    for (int k0 = 0; k0 < Kd; k0 += BKT) {
        float4 av = make_float4(0.f, 0.f, 0.f, 0.f);
        if (row0 + arow < M)
            av = *reinterpret_cast<const float4*>(A + (long long)(row0 + arow) * lda + (k0 + acol));
        As[acol + 0][arow] = av.x;
        As[acol + 1][arow] = av.y;
        As[acol + 2][arow] = av.z;
        As[acol + 3][arow] = av.w;

        if (TB) {
            float4 bv = make_float4(0.f, 0.f, 0.f, 0.f);
            if (col0 + arow < N)
                bv = *reinterpret_cast<const float4*>(B + (long long)(col0 + arow) * ldb + (k0 + acol));
            Bs[acol + 0][arow] = bv.x;
            Bs[acol + 1][arow] = bv.y;
            Bs[acol + 2][arow] = bv.z;
            Bs[acol + 3][arow] = bv.w;
        } else {
            float4 bv = make_float4(0.f, 0.f, 0.f, 0.f);
            if (col0 + bncol < N)
                bv = *reinterpret_cast<const float4*>(B + (long long)(k0 + bkrow) * ldb + (col0 + bncol));
            *reinterpret_cast<float4*>(&Bs[bkrow][bncol]) = bv;
        }
        __syncthreads();

#pragma unroll
        for (int kk = 0; kk < BKT; kk++) {
            float a[8], bb[8];
            *reinterpret_cast<float4*>(&a[0])  = *reinterpret_cast<const float4*>(&As[kk][ty * 8]);
            *reinterpret_cast<float4*>(&a[4])  = *reinterpret_cast<const float4*>(&As[kk][ty * 8 + 4]);
            *reinterpret_cast<float4*>(&bb[0]) = *reinterpret_cast<const float4*>(&Bs[kk][tx * 8]);
            *reinterpret_cast<float4*>(&bb[4]) = *reinterpret_cast<const float4*>(&Bs[kk][tx * 8 + 4]);
#pragma unroll
            for (int i = 0; i < 8; i++)
#pragma unroll
                for (int j = 0; j < 8; j++) acc[i][j] = fmaf(a[i], bb[j], acc[i][j]);
        }
        __syncthreads();
    }

#pragma unroll
    for (int i = 0; i < 8; i++) {
        int r = row0 + ty * 8 + i;
        if (r >= M) continue;
#pragma unroll
        for (int j = 0; j < 8; j++) {
            int c = col0 + tx * 8 + j;
            if (c >= N) continue;
            float v = alpha * acc[i][j];
            if (R) v += R[(long long)r * ldr + c];
            C[(long long)r * ldc + c] = v;
        }
    }
}

// ---------------- RMSNorm ----------------
__global__ void rmsnorm_kernel(const float* __restrict__ x, const float* __restrict__ g,
                               float* __restrict__ out)
{
    int t = blockIdx.x, tid = threadIdx.x;
    const float* xr = x + (size_t)t * HH;
    float* orow = out + (size_t)t * HH;
    __shared__ float red[256];
    float s = 0.f;
    for (int i = tid; i < HH; i += 256) { float v = xr[i]; s += v * v; }
    red[tid] = s; __syncthreads();
    for (int st = 128; st > 0; st >>= 1) { if (tid < st) red[tid] += red[tid + st]; __syncthreads(); }
    float inv = rsqrtf(red[0] / (float)HH + 1e-6f);
    for (int i = tid; i < HH; i += 256) orow[i] = xr[i] * inv * g[i];
}

// ---------------- causal softmax (in-place on one hq row) ----------------
__global__ void softmax_causal_kernel(float* __restrict__ scores)
{
    size_t rowid = blockIdx.x;                  // head*T + q
    int q = (int)(rowid % TT);
    float* row = scores + rowid * (size_t)TT;
    int len = q + 1;
    int tid = threadIdx.x;
    __shared__ float red[256];

    float m = -3.4e38f;
    for (int i = tid; i < len; i += 256) m = fmaxf(m, row[i]);
    red[tid] = m; __syncthreads();
    for (int st = 128; st > 0; st >>= 1) { if (tid < st) red[tid] = fmaxf(red[tid], red[tid + st]); __syncthreads(); }
    m = red[0]; __syncthreads();

    float s = 0.f;
    for (int i = tid; i < len; i += 256) { float e = __expf(row[i] - m); row[i] = e; s += e; }
    red[tid] = s; __syncthreads();
    for (int st = 128; st > 0; st >>= 1) { if (tid < st) red[tid] += red[tid + st]; __syncthreads(); }
    float inv = 1.0f / red[0];

    for (int i = tid; i < len; i += 256) row[i] *= inv;
    for (int i = len + tid; i < TT; i += 256) row[i] = 0.f;   // masked tail for PV GEMM
}

// ---------------- gating: top-8 on logits, softmax weights over selected ----------------
__global__ void gate_topk_kernel(const float* __restrict__ logits,
                                 int* __restrict__ ids, float* __restrict__ wts)
{
    int t = blockIdx.x, lane = threadIdx.x;
    float v0 = logits[(size_t)t * EE + lane];
    float v1 = logits[(size_t)t * EE + 32 + lane];
    float selv[KTOP]; int seli[KTOP];
    for (int r = 0; r < KTOP; r++) {
        float bv; int bi;
        if (v0 >= v1) { bv = v0; bi = lane; } else { bv = v1; bi = lane + 32; }
        for (int o = 16; o > 0; o >>= 1) {
            float ov = __shfl_xor_sync(0xffffffffu, bv, o);
            int   oi = __shfl_xor_sync(0xffffffffu, bi, o);
            if (ov > bv || (ov == bv && oi < bi)) { bv = ov; bi = oi; }  // tie: lower idx (jax)
        }
        selv[r] = bv; seli[r] = bi;
        if (bi == lane)      v0 = -3.4e38f;
        if (bi == lane + 32) v1 = -3.4e38f;
    }
    if (lane == 0) {
        float m = selv[0], s = 0.f, w[KTOP];
        for (int r = 0; r < KTOP; r++) { w[r] = __expf(selv[r] - m); s += w[r]; }
        float inv = 1.f / s;
        for (int r = 0; r < KTOP; r++) { ids[t * KTOP + r] = seli[r]; wts[t * KTOP + r] = w[r] * inv; }
    }
}

// ---------------- per-expert capacity scan over flattened (t,k) order ----------------
__global__ void dispatch_kernel(const int* __restrict__ ids, int* __restrict__ pos,
                                int* __restrict__ cnt)
{
    int e = blockIdx.x;
    int tid = threadIdx.x, lane = tid & 31, w = tid >> 5;
    __shared__ int wt[8];
    __shared__ int base;
    if (tid == 0) base = 0;
    __syncthreads();
    for (int f0 = 0; f0 < TT * KTOP; f0 += 256) {
        int f = f0 + tid;
        int match = (ids[f] == e) ? 1 : 0;
        unsigned m = __ballot_sync(0xffffffffu, match);
        if (lane == 0) wt[w] = __popc(m);
        int wexcl = __popc(m & ((1u << lane) - 1u));
        __syncthreads();
        int off = 0; for (int i = 0; i < w; i++) off += wt[i];
        int tot = 0; for (int i = 0; i < 8; i++) tot += wt[i];
        if (match) {
            int p = base + off + wexcl;
            pos[f] = (p < CAPP) ? p : -1;
        }
        __syncthreads();
        if (tid == 0) base += tot;
        __syncthreads();
    }
    if (tid == 0) cnt[e] = (base < CAPP) ? base : CAPP;
}

// ---------------- zero / gather / activations / combine ----------------
__global__ void zero_kernel(float4* __restrict__ p, long long n4)
{
    long long i = (long long)blockIdx.x * blockDim.x + threadIdx.x;
    long long stride = (long long)gridDim.x * blockDim.x;
    for (; i < n4; i += stride) p[i] = make_float4(0.f, 0.f, 0.f, 0.f);
}

__global__ void gather_kernel(const float* __restrict__ hn2, const int* __restrict__ ids,
                              const int* __restrict__ pos, float* __restrict__ buf)
{
    int f = blockIdx.x;
    int p = pos[f];
    if (p < 0) return;
    int e = ids[f], t = f / KTOP;
    const float4* src = reinterpret_cast<const float4*>(hn2 + (size_t)t * HH);
    float4* dst = reinterpret_cast<float4*>(buf + ((size_t)e * CAPP + p) * HH);
    for (int i = threadIdx.x; i < HH / 4; i += 256) dst[i] = src[i];
}

__global__ void expert_act_kernel(const float* __restrict__ gu, float* __restrict__ act,
                                  const int* __restrict__ cnt)
{
    int ec = blockIdx.x;
    int c = ec & (CAPP - 1);
    int e = ec >> 9;                    // CAP = 512
    if (c >= cnt[e]) return;
    const float* gr = gu + (size_t)ec * (2 * II);
    float* ar = act + (size_t)ec * II;
    for (int i = threadIdx.x; i < II; i += 256) {
        float gv = gr[i], uv = gr[II + i];
        ar[i] = gv / (1.f + __expf(-gv)) * uv;   // silu(g) * u
    }
}

__global__ void shared_act_kernel(const float* __restrict__ sgu, float* __restrict__ sact)
{
    int t = blockIdx.x;
    const float* gr = sgu + (size_t)t * (2 * SII);
    float* ar = sact + (size_t)t * SII;
    for (int i = threadIdx.x; i < SII; i += 256) {
        float gv = gr[i], uv = gr[SII + i];
        ar[i] = gv / (1.f + __expf(-gv)) * uv;
    }
}

__global__ void combine_kernel(const float* __restrict__ sres, const float* __restrict__ y,
                               const int* __restrict__ ids, const float* __restrict__ wts,
                               const int* __restrict__ pos, float* __restrict__ out)
{
    int t = blockIdx.x;
    __shared__ int se[KTOP], sp[KTOP];
    __shared__ float sw[KTOP];
    if (threadIdx.x < KTOP) {
        se[threadIdx.x] = ids[t * KTOP + threadIdx.x];
        sp[threadIdx.x] = pos[t * KTOP + threadIdx.x];
        sw[threadIdx.x] = wts[t * KTOP + threadIdx.x];
    }
    __syncthreads();
    for (int h = threadIdx.x; h < HH; h += 256) {
        float acc = sres[(size_t)t * HH + h];
#pragma unroll
        for (int k = 0; k < KTOP; k++)
            if (sp[k] >= 0)
                acc += y[((size_t)se[k] * CAPP + sp[k]) * HH + h] * sw[k];
        out[(size_t)t * HH + h] = acc;
    }
}

// ---------------- host-side launch ----------------
static inline void gemm(bool tb,
    const float* A, int lda, long long sA,
    const float* B, int ldb, long long sB,
    float*       C, int ldc, long long sC,
    const float* R, int ldr, long long sR,
    int M, int N, int Kd, float alpha, const int* rl, int batch)
{
    dim3 grid((N + BN - 1) / BN, (M + BM - 1) / BM, batch);
    if (tb) sgemm_k<true ><<<grid, 256>>>(A, lda, sA, B, ldb, sB, C, ldc, sC, R, ldr, sR, M, N, Kd, alpha, rl);
    else    sgemm_k<false><<<grid, 256>>>(A, lda, sA, B, ldb, sB, C, ldc, sC, R, ldr, sR, M, N, Kd, alpha, rl);
}

extern "C" void kernel_launch(void* const* d_in, const int* in_sizes, int n_in,
                              void* d_out, int out_size)
{
    const float* x      = (const float*)d_in[0];
    const float* w_qkv  = (const float*)d_in[1];
    const float* w_o    = (const float*)d_in[2];
    const float* pre_g  = (const float*)d_in[3];
    const float* post_g = (const float*)d_in[4];
    const float* w_gate = (const float*)d_in[5];
    const float* w1     = (const float*)d_in[6];
    const float* w2     = (const float*)d_in[7];
    const float* sw13   = (const float*)d_in[8];
    const float* sw2    = (const float*)d_in[9];
    float* out = (float*)d_out;

    float *hn1, *qkv, *scores, *attn, *x2, *hn2, *logits, *wts, *buf, *gu, *eact, *y, *sgu, *sact, *sres;
    int *ids, *pos, *cnt;
    cudaGetSymbolAddress((void**)&hn1,    g_hn1);
    cudaGetSymbolAddress((void**)&qkv,    g_qkv);
    cudaGetSymbolAddress((void**)&scores, g_scores);
    cudaGetSymbolAddress((void**)&attn,   g_attn);
    cudaGetSymbolAddress((void**)&x2,     g_x2);
    cudaGetSymbolAddress((void**)&hn2,    g_hn2);
    cudaGetSymbolAddress((void**)&logits, g_logits);
    cudaGetSymbolAddress((void**)&ids,    g_ids);
    cudaGetSymbolAddress((void**)&wts,    g_wts);
    cudaGetSymbolAddress((void**)&pos,    g_pos);
    cudaGetSymbolAddress((void**)&cnt,    g_cnt);
    cudaGetSymbolAddress((void**)&buf,    g_buf);
    cudaGetSymbolAddress((void**)&gu,     g_gu);
    cudaGetSymbolAddress((void**)&eact,   g_eact);
    cudaGetSymbolAddress((void**)&y,      g_y);
    cudaGetSymbolAddress((void**)&sgu,    g_sgu);
    cudaGetSymbolAddress((void**)&sact,   g_sact);
    cudaGetSymbolAddress((void**)&sres,   g_sres);

    const float sc = 0.08838834764831845f;   // DH^-0.5

    // 1) pre-LN
    rmsnorm_kernel<<<TT, 256>>>(x, pre_g, hn1);
    // 2) qkv = hn1 @ w_qkv          (NN)
    gemm(false, hn1, HH, 0, w_qkv, 3 * HH, 0, qkv, 3 * HH, 0, nullptr, 0, 0,
         TT, 3 * HH, HH, 1.f, nullptr, 1);
    // 3) scores[h] = Q_h K_h^T * sc (NT, batched over heads)
    gemm(true, qkv, 3 * HH, DHH, qkv + HH, 3 * HH, DHH, scores, TT, (long long)TT * TT,
         nullptr, 0, 0, TT, TT, DHH, sc, nullptr, NHH);
    // 4) causal softmax in-place
    softmax_causal_kernel<<<NHH * TT, 256>>>(scores);
    // 5) attn[h] = P_h V_h          (NN, batched)
    gemm(false, scores, TT, (long long)TT * TT, qkv + 2 * HH, 3 * HH, DHH, attn, HH, DHH,
         nullptr, 0, 0, TT, DHH, TT, 1.f, nullptr, NHH);
    // 6) x2 = x + attn @ w_o        (NN, fused residual)
    gemm(false, attn, HH, 0, w_o, HH, 0, x2, HH, 0, x, HH, 0,
         TT, HH, HH, 1.f, nullptr, 1);
    // 7) post-LN
    rmsnorm_kernel<<<TT, 256>>>(x2, post_g, hn2);
    // 8) gate logits = hn2 @ w_gate^T (NT)
    gemm(true, hn2, HH, 0, w_gate, HH, 0, logits, EE, 0, nullptr, 0, 0,
         TT, EE, HH, 1.f, nullptr, 1);
    // 9) top-8 + weights
    gate_topk_kernel<<<TT, 32>>>(logits, ids, wts);
    // 10) capacity dispatch (per-expert ordered scan)
    dispatch_kernel<<<EE, 256>>>(ids, pos, cnt);
    // 11) zero + gather into expert buffers
    zero_kernel<<<4096, 256>>>((float4*)buf, (long long)EE * CAPP * HH / 4);
    gather_kernel<<<TT * KTOP, 256>>>(hn2, ids, pos, buf);
    // 12) expert GEMM1: gu[e] = buf[e] @ w1[e]^T   (NT, count-guarded)
    gemm(true, buf, HH, (long long)CAPP * HH, w1, HH, (long long)2 * II * HH,
         gu, 2 * II, (long long)CAPP * 2 * II, nullptr, 0, 0,
         CAPP, 2 * II, HH, 1.f, cnt, EE);
    // 13) silu(g)*u per expert row
    expert_act_kernel<<<EE * CAPP, 256>>>(gu, eact, cnt);
    // 14) expert GEMM2: y[e] = eact[e] @ w2[e]^T   (NT, count-guarded)
    gemm(true, eact, II, (long long)CAPP * II, w2, II, (long long)HH * II,
         y, HH, (long long)CAPP * HH, nullptr, 0, 0,
         CAPP, HH, II, 1.f, cnt, EE);
    // 15) shared MLP: sgu = hn2 @ w13^T (NT)
    gemm(true, hn2, HH, 0, sw13, HH, 0, sgu, 2 * SII, 0, nullptr, 0, 0,
         TT, 2 * SII, HH, 1.f, nullptr, 1);
    shared_act_kernel<<<TT, 256>>>(sgu, sact);
    // 16) sres = x2 + sact @ sw2^T  (NT, fused residual)
    gemm(true, sact, SII, 0, sw2, SII, 0, sres, HH, 0, x2, HH, 0,
         TT, HH, SII, 1.f, nullptr, 1);
    // 17) final: out = sres + sum_k w_k * y[e_k, pos_k]
    combine_kernel<<<TT, 256>>>(sres, y, ids, wts, pos, out);
}